// round 3
// baseline (speedup 1.0000x reference)
#include <cuda_runtime.h>
#include <cstdint>

#define N_NODES 50000
#define N_EDGES 800000
#define D_IN    256
#define D_OUT   128

// ---------------- scratch (no allocations allowed) ----------------
__device__ int   g_deg   [N_NODES];
__device__ float g_dinv  [N_NODES];
__device__ int   g_rowptr[N_NODES + 1];
__device__ int   g_cursor[N_NODES];
__device__ int   g_col   [N_EDGES];
__device__ float g_h     [(size_t)N_NODES * D_OUT];   // 25.6 MB

// ---------------- 1a. zero degree ----------------
__global__ void k_zero(int* deg) {
    int i = blockIdx.x * blockDim.x + threadIdx.x;
    if (i < N_NODES) deg[i] = 0;
}

// ---------------- 1b. histogram of dst ----------------
__global__ void k_count(const int* __restrict__ ei, int* deg) {
    int e = blockIdx.x * blockDim.x + threadIdx.x;
    if (e < N_EDGES) atomicAdd(&deg[ei[N_EDGES + e]], 1);
}

// ---------------- 2. single-block exclusive scan + dinv ----------------
__global__ __launch_bounds__(1024) void k_scan(const int* __restrict__ deg,
                                               float* __restrict__ dinv,
                                               int* __restrict__ rowptr,
                                               int* __restrict__ cursor) {
    __shared__ int ps[1024];
    const int CH = (N_NODES + 1023) / 1024;   // 49
    int t  = threadIdx.x;
    int lo = t * CH;
    int hi = min(lo + CH, N_NODES);
    int s = 0;
    for (int i = lo; i < hi; i++) s += deg[i];
    ps[t] = s;
    __syncthreads();
    // Hillis-Steele inclusive scan over 1024 partials
    for (int off = 1; off < 1024; off <<= 1) {
        int v = (t >= off) ? ps[t - off] : 0;
        __syncthreads();
        ps[t] += v;
        __syncthreads();
    }
    int run = (t > 0) ? ps[t - 1] : 0;        // exclusive prefix for this chunk
    for (int i = lo; i < hi; i++) {
        rowptr[i] = run;
        cursor[i] = run;
        int d = deg[i];
        run += d;
        dinv[i] = rsqrtf((float)d + 1.0f);    // +1 = self loop
    }
    if (t == 1023) rowptr[N_NODES] = ps[1023];
}

// ---------------- 3. bucket fill (counting sort by dst) ----------------
__global__ void k_fill(const int* __restrict__ ei, int* __restrict__ cursor,
                       int* __restrict__ col) {
    int e = blockIdx.x * blockDim.x + threadIdx.x;
    if (e < N_EDGES) {
        int src = ei[e];
        int dst = ei[N_EDGES + e];
        int pos = atomicAdd(&cursor[dst], 1);
        col[pos] = src;
    }
}

// ---------------- 4. GEMM h = x @ W  (fp32, 64x128x32 tiles) ----------------
__global__ __launch_bounds__(256) void k_gemm(const float* __restrict__ X,
                                              const float* __restrict__ W,
                                              float* __restrict__ H) {
    __shared__ float As[64][32];
    __shared__ float Bs[32][128];

    const int tid = threadIdx.x;
    const int tx  = tid & 31;
    const int ty  = tid >> 5;
    const int m0  = blockIdx.x * 64;

    float acc[8][4];
#pragma unroll
    for (int i = 0; i < 8; i++)
#pragma unroll
        for (int j = 0; j < 4; j++) acc[i][j] = 0.0f;

    const float4* X4 = (const float4*)X;
    const float4* W4 = (const float4*)W;

    for (int k0 = 0; k0 < D_IN; k0 += 32) {
#pragma unroll
        for (int p = 0; p < 2; p++) {
            int idx = tid + p * 256;
            int r   = idx >> 3;
            int c4  = idx & 7;
            int gr  = m0 + r;
            float4 v = make_float4(0.f, 0.f, 0.f, 0.f);
            if (gr < N_NODES) v = X4[(size_t)gr * 64 + (k0 >> 2) + c4];
            As[r][c4 * 4 + 0] = v.x;
            As[r][c4 * 4 + 1] = v.y;
            As[r][c4 * 4 + 2] = v.z;
            As[r][c4 * 4 + 3] = v.w;
        }
#pragma unroll
        for (int p = 0; p < 4; p++) {
            int idx = tid + p * 256;
            int r   = idx >> 5;
            int c4  = idx & 31;
            ((float4*)&Bs[r][0])[c4] = W4[(size_t)(k0 + r) * 32 + c4];
        }
        __syncthreads();

#pragma unroll
        for (int k = 0; k < 32; k++) {
            float a[8];
#pragma unroll
            for (int i = 0; i < 8; i++) a[i] = As[ty * 8 + i][k];
            float4 b4 = ((const float4*)&Bs[k][0])[tx];
#pragma unroll
            for (int i = 0; i < 8; i++) {
                acc[i][0] += a[i] * b4.x;
                acc[i][1] += a[i] * b4.y;
                acc[i][2] += a[i] * b4.z;
                acc[i][3] += a[i] * b4.w;
            }
        }
        __syncthreads();
    }

    float4* H4 = (float4*)H;
#pragma unroll
    for (int i = 0; i < 8; i++) {
        int gr = m0 + ty * 8 + i;
        if (gr < N_NODES) {
            H4[(size_t)gr * 32 + tx] =
                make_float4(acc[i][0], acc[i][1], acc[i][2], acc[i][3]);
        }
    }
}

// ---------------- 5. pull-mode gather + self-loop + bias + PReLU ----------------
// one warp per node; lane owns 4 channels (float4)
__global__ __launch_bounds__(256) void k_gather(const int* __restrict__ rowptr,
                                                const int* __restrict__ col,
                                                const float* __restrict__ dinv,
                                                const float* __restrict__ H,
                                                const float* __restrict__ b,
                                                const float* __restrict__ pa,
                                                float* __restrict__ out) {
    int node = blockIdx.x * 8 + (threadIdx.x >> 5);
    int lane = threadIdx.x & 31;
    if (node >= N_NODES) return;

    const float4* H4 = (const float4*)H;
    float di = dinv[node];

    // self-loop term: dinv_i * h_i (outer dinv_i applied at the end)
    float4 hs = H4[(size_t)node * 32 + lane];
    float4 acc = make_float4(hs.x * di, hs.y * di, hs.z * di, hs.w * di);

    int r0 = rowptr[node];
    int r1 = rowptr[node + 1];

    for (int base = r0; base < r1; base += 32) {
        int e    = base + lane;
        int srcL = (e < r1) ? col[e] : 0;
        float sL = (e < r1) ? dinv[srcL] : 0.0f;
        int cnt  = min(32, r1 - base);
        for (int j = 0; j < cnt; j++) {
            int   src = __shfl_sync(0xffffffffu, srcL, j);
            float sc  = __shfl_sync(0xffffffffu, sL,  j);
            float4 v  = H4[(size_t)src * 32 + lane];
            acc.x += v.x * sc;
            acc.y += v.y * sc;
            acc.z += v.z * sc;
            acc.w += v.w * sc;
        }
    }

    float4 bb = ((const float4*)b)[lane];
    float4 aa = ((const float4*)pa)[lane];
    float4 o;
    o.x = acc.x * di + bb.x;
    o.y = acc.y * di + bb.y;
    o.z = acc.z * di + bb.z;
    o.w = acc.w * di + bb.w;
    o.x = o.x > 0.f ? o.x : aa.x * o.x;
    o.y = o.y > 0.f ? o.y : aa.y * o.y;
    o.z = o.z > 0.f ? o.z : aa.z * o.z;
    o.w = o.w > 0.f ? o.w : aa.w * o.w;
    ((float4*)out)[(size_t)node * 32 + lane] = o;
}

// ---------------- launch ----------------
extern "C" void kernel_launch(void* const* d_in, const int* in_sizes, int n_in,
                              void* d_out, int out_size) {
    const float* x  = (const float*)d_in[0];
    const int*   ei = (const int*)d_in[1];     // [2, N_EDGES] int32
    const float* W  = (const float*)d_in[2];
    const float* b  = (const float*)d_in[3];
    const float* pa = (const float*)d_in[4];
    float* out = (float*)d_out;

    int*   deg;    cudaGetSymbolAddress((void**)&deg,    g_deg);
    float* dinv;   cudaGetSymbolAddress((void**)&dinv,   g_dinv);
    int*   rowptr; cudaGetSymbolAddress((void**)&rowptr, g_rowptr);
    int*   cursor; cudaGetSymbolAddress((void**)&cursor, g_cursor);
    int*   col;    cudaGetSymbolAddress((void**)&col,    g_col);
    float* h;      cudaGetSymbolAddress((void**)&h,      g_h);

    k_zero <<<(N_NODES + 255) / 256, 256>>>(deg);
    k_count<<<(N_EDGES + 255) / 256, 256>>>(ei, deg);
    k_scan <<<1, 1024>>>(deg, dinv, rowptr, cursor);
    k_fill <<<(N_EDGES + 255) / 256, 256>>>(ei, cursor, col);

    k_gemm <<<(N_NODES + 63) / 64, 256>>>(x, W, h);

    k_gather<<<(N_NODES + 7) / 8, 256>>>(rowptr, col, dinv, h, b, pa, out);
}

// round 4
// speedup vs baseline: 1.5252x; 1.5252x over previous
#include <cuda_runtime.h>
#include <cstdint>

#define N_NODES 50000
#define N_EDGES 800000
#define D_IN    256
#define D_OUT   128

// ---------------- scratch (no allocations allowed) ----------------
__device__ int   g_deg   [N_NODES];
__device__ float g_dinv  [N_NODES];
__device__ int   g_rowptr[N_NODES + 1];
__device__ int   g_cursor[N_NODES];
__device__ int   g_col   [N_EDGES];
__device__ float g_h     [(size_t)N_NODES * D_OUT];   // 25.6 MB

// ---------------- 1a. zero degree ----------------
__global__ void k_zero(int* deg) {
    int i = blockIdx.x * blockDim.x + threadIdx.x;
    if (i < N_NODES) deg[i] = 0;
}

// ---------------- 1b. histogram of dst ----------------
__global__ void k_count(const int* __restrict__ ei, int* deg) {
    int e = blockIdx.x * blockDim.x + threadIdx.x;
    if (e < N_EDGES) atomicAdd(&deg[ei[N_EDGES + e]], 1);
}

// ---------------- 2. single-block exclusive scan + dinv ----------------
__global__ __launch_bounds__(1024) void k_scan(const int* __restrict__ deg,
                                               float* __restrict__ dinv,
                                               int* __restrict__ rowptr,
                                               int* __restrict__ cursor) {
    __shared__ int ps[1024];
    const int CH = (N_NODES + 1023) / 1024;   // 49
    int t  = threadIdx.x;
    int lo = t * CH;
    int hi = min(lo + CH, N_NODES);
    int s = 0;
    for (int i = lo; i < hi; i++) s += deg[i];
    ps[t] = s;
    __syncthreads();
    for (int off = 1; off < 1024; off <<= 1) {
        int v = (t >= off) ? ps[t - off] : 0;
        __syncthreads();
        ps[t] += v;
        __syncthreads();
    }
    int run = (t > 0) ? ps[t - 1] : 0;
    for (int i = lo; i < hi; i++) {
        rowptr[i] = run;
        cursor[i] = run;
        int d = deg[i];
        run += d;
        dinv[i] = rsqrtf((float)d + 1.0f);    // +1 = self loop
    }
    if (t == 1023) rowptr[N_NODES] = ps[1023];
}

// ---------------- 3. bucket fill (counting sort by dst) ----------------
__global__ void k_fill(const int* __restrict__ ei, int* __restrict__ cursor,
                       int* __restrict__ col) {
    int e = blockIdx.x * blockDim.x + threadIdx.x;
    if (e < N_EDGES) {
        int src = ei[e];
        int dst = ei[N_EDGES + e];
        int pos = atomicAdd(&cursor[dst], 1);
        col[pos] = src;
    }
}

// ---------------- 4. GEMM h = x @ W  (fp32, 64x128x32 tiles) ----------------
__global__ __launch_bounds__(256) void k_gemm(const float* __restrict__ X,
                                              const float* __restrict__ W,
                                              float* __restrict__ H) {
    __shared__ float As[64][32];
    __shared__ float Bs[32][128];

    const int tid = threadIdx.x;
    const int tx  = tid & 31;
    const int ty  = tid >> 5;
    const int m0  = blockIdx.x * 64;

    float acc[8][4];
#pragma unroll
    for (int i = 0; i < 8; i++)
#pragma unroll
        for (int j = 0; j < 4; j++) acc[i][j] = 0.0f;

    const float4* X4 = (const float4*)X;
    const float4* W4 = (const float4*)W;

    for (int k0 = 0; k0 < D_IN; k0 += 32) {
#pragma unroll
        for (int p = 0; p < 2; p++) {
            int idx = tid + p * 256;
            int r   = idx >> 3;
            int c4  = idx & 7;
            int gr  = m0 + r;
            float4 v = make_float4(0.f, 0.f, 0.f, 0.f);
            if (gr < N_NODES) v = X4[(size_t)gr * 64 + (k0 >> 2) + c4];
            As[r][c4 * 4 + 0] = v.x;
            As[r][c4 * 4 + 1] = v.y;
            As[r][c4 * 4 + 2] = v.z;
            As[r][c4 * 4 + 3] = v.w;
        }
#pragma unroll
        for (int p = 0; p < 4; p++) {
            int idx = tid + p * 256;
            int r   = idx >> 5;
            int c4  = idx & 31;
            ((float4*)&Bs[r][0])[c4] = W4[(size_t)(k0 + r) * 32 + c4];
        }
        __syncthreads();

#pragma unroll
        for (int k = 0; k < 32; k++) {
            float a[8];
#pragma unroll
            for (int i = 0; i < 8; i++) a[i] = As[ty * 8 + i][k];
            float4 b4 = ((const float4*)&Bs[k][0])[tx];
#pragma unroll
            for (int i = 0; i < 8; i++) {
                acc[i][0] += a[i] * b4.x;
                acc[i][1] += a[i] * b4.y;
                acc[i][2] += a[i] * b4.z;
                acc[i][3] += a[i] * b4.w;
            }
        }
        __syncthreads();
    }

    float4* H4 = (float4*)H;
#pragma unroll
    for (int i = 0; i < 8; i++) {
        int gr = m0 + ty * 8 + i;
        if (gr < N_NODES) {
            H4[(size_t)gr * 32 + tx] =
                make_float4(acc[i][0], acc[i][1], acc[i][2], acc[i][3]);
        }
    }
}

// ---------------- 5. pull-mode gather + self-loop + bias + PReLU ----------------
// one warp per node; lane owns 4 channels (float4).
// Inner loop batches 8 edges with unrolled independent loads -> MLP=8.
__global__ __launch_bounds__(256) void k_gather(const int* __restrict__ rowptr,
                                                const int* __restrict__ col,
                                                const float* __restrict__ dinv,
                                                const float* __restrict__ H,
                                                const float* __restrict__ b,
                                                const float* __restrict__ pa,
                                                float* __restrict__ out) {
    int node = blockIdx.x * 8 + (threadIdx.x >> 5);
    int lane = threadIdx.x & 31;
    if (node >= N_NODES) return;

    const float4* H4 = (const float4*)H;
    float di = dinv[node];

    // self-loop term (outer dinv_i applied at the end)
    float4 hs = H4[(size_t)node * 32 + lane];
    float4 acc = make_float4(hs.x * di, hs.y * di, hs.z * di, hs.w * di);

    int r0 = rowptr[node];
    int r1 = rowptr[node + 1];

    for (int base = r0; base < r1; base += 32) {
        int e    = base + lane;
        int srcL = (e < r1) ? col[e] : 0;
        float sL = (e < r1) ? dinv[srcL] : 0.0f;
        int cnt  = min(32, r1 - base);

        int j = 0;
        // unrolled batches of 8: independent loads -> deep MLP
        for (; j + 8 <= cnt; j += 8) {
            float4 v[8];
            float  sc[8];
#pragma unroll
            for (int t = 0; t < 8; t++) {
                int src = __shfl_sync(0xffffffffu, srcL, j + t);
                sc[t]   = __shfl_sync(0xffffffffu, sL,  j + t);
                v[t]    = H4[(size_t)src * 32 + lane];
            }
#pragma unroll
            for (int t = 0; t < 8; t++) {
                acc.x += v[t].x * sc[t];
                acc.y += v[t].y * sc[t];
                acc.z += v[t].z * sc[t];
                acc.w += v[t].w * sc[t];
            }
        }
        // tail batch of 4
        for (; j + 4 <= cnt; j += 4) {
            float4 v[4];
            float  sc[4];
#pragma unroll
            for (int t = 0; t < 4; t++) {
                int src = __shfl_sync(0xffffffffu, srcL, j + t);
                sc[t]   = __shfl_sync(0xffffffffu, sL,  j + t);
                v[t]    = H4[(size_t)src * 32 + lane];
            }
#pragma unroll
            for (int t = 0; t < 4; t++) {
                acc.x += v[t].x * sc[t];
                acc.y += v[t].y * sc[t];
                acc.z += v[t].z * sc[t];
                acc.w += v[t].w * sc[t];
            }
        }
        // scalar tail
        for (; j < cnt; j++) {
            int   src = __shfl_sync(0xffffffffu, srcL, j);
            float sc  = __shfl_sync(0xffffffffu, sL,  j);
            float4 v  = H4[(size_t)src * 32 + lane];
            acc.x += v.x * sc;
            acc.y += v.y * sc;
            acc.z += v.z * sc;
            acc.w += v.w * sc;
        }
    }

    float4 bb = ((const float4*)b)[lane];
    float4 aa = ((const float4*)pa)[lane];
    float4 o;
    o.x = acc.x * di + bb.x;
    o.y = acc.y * di + bb.y;
    o.z = acc.z * di + bb.z;
    o.w = acc.w * di + bb.w;
    o.x = o.x > 0.f ? o.x : aa.x * o.x;
    o.y = o.y > 0.f ? o.y : aa.y * o.y;
    o.z = o.z > 0.f ? o.z : aa.z * o.z;
    o.w = o.w > 0.f ? o.w : aa.w * o.w;
    ((float4*)out)[(size_t)node * 32 + lane] = o;
}

// ---------------- launch ----------------
extern "C" void kernel_launch(void* const* d_in, const int* in_sizes, int n_in,
                              void* d_out, int out_size) {
    const float* x  = (const float*)d_in[0];
    const int*   ei = (const int*)d_in[1];     // [2, N_EDGES] int32
    const float* W  = (const float*)d_in[2];
    const float* b  = (const float*)d_in[3];
    const float* pa = (const float*)d_in[4];
    float* out = (float*)d_out;

    int*   deg;    cudaGetSymbolAddress((void**)&deg,    g_deg);
    float* dinv;   cudaGetSymbolAddress((void**)&dinv,   g_dinv);
    int*   rowptr; cudaGetSymbolAddress((void**)&rowptr, g_rowptr);
    int*   cursor; cudaGetSymbolAddress((void**)&cursor, g_cursor);
    int*   col;    cudaGetSymbolAddress((void**)&col,    g_col);
    float* h;      cudaGetSymbolAddress((void**)&h,      g_h);

    k_zero <<<(N_NODES + 255) / 256, 256>>>(deg);
    k_count<<<(N_EDGES + 255) / 256, 256>>>(ei, deg);
    k_scan <<<1, 1024>>>(deg, dinv, rowptr, cursor);
    k_fill <<<(N_EDGES + 255) / 256, 256>>>(ei, cursor, col);

    k_gemm <<<(N_NODES + 63) / 64, 256>>>(x, W, h);

    k_gather<<<(N_NODES + 7) / 8, 256>>>(rowptr, col, dinv, h, b, pa, out);
}

// round 5
// speedup vs baseline: 2.6312x; 1.7251x over previous
#include <cuda_runtime.h>
#include <cstdint>

#define N_NODES 50000
#define N_EDGES 800000
#define D_IN    256
#define D_OUT   128

#define SCAN_BLOCKS ((N_NODES + 1023) / 1024)   // 49

// ---------------- scratch (no allocations allowed) ----------------
__device__ int   g_deg   [N_NODES];
__device__ float g_dinv  [N_NODES];
__device__ int   g_rowptr[N_NODES + 1];
__device__ int   g_cursor[N_NODES];
__device__ int   g_col   [N_EDGES];
__device__ int   g_bsum  [64];
__device__ int   g_boff  [64];
__device__ float g_h     [(size_t)N_NODES * D_OUT];   // 25.6 MB

// ---------------- streams/events for capture-fork (created before capture) --
static cudaStream_t g_s2;
static cudaEvent_t  g_evFork, g_evJoin;
static struct StreamInit {
    StreamInit() {
        cudaStreamCreateWithFlags(&g_s2, cudaStreamNonBlocking);
        cudaEventCreateWithFlags(&g_evFork, cudaEventDisableTiming);
        cudaEventCreateWithFlags(&g_evJoin, cudaEventDisableTiming);
    }
} g_streamInit;

// ---------------- 1a. zero degree ----------------
__global__ void k_zero(int* deg) {
    int i = blockIdx.x * blockDim.x + threadIdx.x;
    if (i < N_NODES) deg[i] = 0;
}

// ---------------- 1b. histogram of dst ----------------
__global__ void k_count(const int* __restrict__ ei, int* deg) {
    int e = blockIdx.x * blockDim.x + threadIdx.x;
    if (e < N_EDGES) atomicAdd(&deg[ei[N_EDGES + e]], 1);
}

// ---------------- 2a. per-block partial sums (1024 deg per block) -----------
__global__ __launch_bounds__(256) void k_scan1(const int* __restrict__ deg,
                                               int* __restrict__ bsum) {
    __shared__ int ws[8];
    int b = blockIdx.x, t = threadIdx.x;
    int base = b * 1024 + t * 4;
    int s = 0;
#pragma unroll
    for (int q = 0; q < 4; q++) {
        int i = base + q;
        if (i < N_NODES) s += deg[i];
    }
    for (int o = 16; o; o >>= 1) s += __shfl_down_sync(0xffffffffu, s, o);
    if ((t & 31) == 0) ws[t >> 5] = s;
    __syncthreads();
    if (t == 0) {
        int v = 0;
#pragma unroll
        for (int w = 0; w < 8; w++) v += ws[w];
        bsum[b] = v;
    }
}

// ---------------- 2b. tiny serial scan of 49 block sums ----------------
__global__ void k_scan2(const int* __restrict__ bsum, int* __restrict__ boff,
                        int* __restrict__ rowptr) {
    if (threadIdx.x == 0) {
        int run = 0;
#pragma unroll
        for (int b = 0; b < SCAN_BLOCKS; b++) {
            boff[b] = run;
            run += bsum[b];
        }
        rowptr[N_NODES] = N_EDGES;
    }
}

// ---------------- 2c. rescan + write rowptr/cursor/dinv ----------------
__global__ __launch_bounds__(256) void k_scan3(const int* __restrict__ deg,
                                               const int* __restrict__ boff,
                                               int* __restrict__ rowptr,
                                               int* __restrict__ cursor,
                                               float* __restrict__ dinv) {
    __shared__ int ws[8];
    int b = blockIdx.x, t = threadIdx.x;
    int base = b * 1024 + t * 4;
    int d[4];
    int s = 0;
#pragma unroll
    for (int q = 0; q < 4; q++) {
        int i = base + q;
        d[q] = (i < N_NODES) ? deg[i] : 0;
        s += d[q];
    }
    int lane = t & 31, w = t >> 5;
    int inc = s;
    for (int o = 1; o < 32; o <<= 1) {
        int v = __shfl_up_sync(0xffffffffu, inc, o);
        if (lane >= o) inc += v;
    }
    if (lane == 31) ws[w] = inc;
    __syncthreads();
    if (t < 8) {
        int v = ws[t];
        int p = v;
        for (int o = 1; o < 8; o <<= 1) {
            int u = __shfl_up_sync(0xffu, p, o);
            if (t >= o) p += u;
        }
        ws[t] = p - v;   // exclusive warp offset
    }
    __syncthreads();
    int off = boff[b] + ws[w] + (inc - s);
#pragma unroll
    for (int q = 0; q < 4; q++) {
        int i = base + q;
        if (i < N_NODES) {
            rowptr[i] = off;
            cursor[i] = off;
            dinv[i]   = rsqrtf((float)d[q] + 1.0f);   // +1 = self loop
            off += d[q];
        }
    }
}

// ---------------- 3. bucket fill (counting sort by dst) ----------------
__global__ void k_fill(const int* __restrict__ ei, int* __restrict__ cursor,
                       int* __restrict__ col) {
    int e = blockIdx.x * blockDim.x + threadIdx.x;
    if (e < N_EDGES) {
        int src = ei[e];
        int dst = ei[N_EDGES + e];
        int pos = atomicAdd(&cursor[dst], 1);
        col[pos] = src;
    }
}

// ---------------- 4. GEMM h = x @ W  (128x128x16, double-buffered) ----------
__global__ __launch_bounds__(256) void k_gemm(const float* __restrict__ X,
                                              const float* __restrict__ W,
                                              float* __restrict__ H) {
    __shared__ float Ast[2][16][132];   // transposed A, padded (+4)
    __shared__ float Bs [2][16][128];

    const int tid = threadIdx.x;
    const int tx  = tid & 15;           // 0..15 col group
    const int ty  = tid >> 4;           // 0..15 row group
    const int m0  = blockIdx.x * 128;

    float acc[8][8];
#pragma unroll
    for (int i = 0; i < 8; i++)
#pragma unroll
        for (int j = 0; j < 8; j++) acc[i][j] = 0.0f;

    const float4* X4 = (const float4*)X;   // row stride 64 float4
    const float4* W4 = (const float4*)W;   // row stride 32 float4

    // prologue: load k-block 0
#pragma unroll
    for (int p = 0; p < 2; p++) {
        int idx = tid + p * 256;           // 0..511
        int r   = idx >> 2;                // 0..127
        int c4  = idx & 3;                 // 0..3
        int gr  = m0 + r;
        float4 v = make_float4(0.f, 0.f, 0.f, 0.f);
        if (gr < N_NODES) v = X4[(size_t)gr * 64 + c4];
        Ast[0][c4 * 4 + 0][r] = v.x;
        Ast[0][c4 * 4 + 1][r] = v.y;
        Ast[0][c4 * 4 + 2][r] = v.z;
        Ast[0][c4 * 4 + 3][r] = v.w;
    }
#pragma unroll
    for (int p = 0; p < 2; p++) {
        int idx = tid + p * 256;
        int r   = idx >> 5;                // 0..15
        int c4  = idx & 31;                // 0..31
        ((float4*)&Bs[0][r][0])[c4] = W4[(size_t)r * 32 + c4];
    }
    __syncthreads();

    int buf = 0;
#pragma unroll 1
    for (int kb = 0; kb < D_IN / 16; kb++) {
        int nbuf = buf ^ 1;
        if (kb + 1 < D_IN / 16) {
            int k0 = (kb + 1) * 16;
#pragma unroll
            for (int p = 0; p < 2; p++) {
                int idx = tid + p * 256;
                int r   = idx >> 2;
                int c4  = idx & 3;
                int gr  = m0 + r;
                float4 v = make_float4(0.f, 0.f, 0.f, 0.f);
                if (gr < N_NODES) v = X4[(size_t)gr * 64 + (k0 >> 2) + c4];
                Ast[nbuf][c4 * 4 + 0][r] = v.x;
                Ast[nbuf][c4 * 4 + 1][r] = v.y;
                Ast[nbuf][c4 * 4 + 2][r] = v.z;
                Ast[nbuf][c4 * 4 + 3][r] = v.w;
            }
#pragma unroll
            for (int p = 0; p < 2; p++) {
                int idx = tid + p * 256;
                int r   = idx >> 5;
                int c4  = idx & 31;
                ((float4*)&Bs[nbuf][r][0])[c4] = W4[(size_t)(k0 + r) * 32 + c4];
            }
        }
#pragma unroll
        for (int k = 0; k < 16; k++) {
            float4 a0 = *(const float4*)&Ast[buf][k][ty * 4];
            float4 a1 = *(const float4*)&Ast[buf][k][ty * 4 + 64];
            float4 b0 = *(const float4*)&Bs[buf][k][tx * 4];
            float4 b1 = *(const float4*)&Bs[buf][k][tx * 4 + 64];
            float ar[8] = {a0.x, a0.y, a0.z, a0.w, a1.x, a1.y, a1.z, a1.w};
            float br[8] = {b0.x, b0.y, b0.z, b0.w, b1.x, b1.y, b1.z, b1.w};
#pragma unroll
            for (int i = 0; i < 8; i++)
#pragma unroll
                for (int j = 0; j < 8; j++)
                    acc[i][j] += ar[i] * br[j];
        }
        __syncthreads();
        buf = nbuf;
    }

    float4* H4 = (float4*)H;
#pragma unroll
    for (int half = 0; half < 2; half++) {
#pragma unroll
        for (int i = 0; i < 4; i++) {
            int gr = m0 + ty * 4 + half * 64 + i;
            if (gr < N_NODES) {
                int ri = half * 4 + i;
                H4[(size_t)gr * 32 + tx] =
                    make_float4(acc[ri][0], acc[ri][1], acc[ri][2], acc[ri][3]);
                H4[(size_t)gr * 32 + tx + 16] =
                    make_float4(acc[ri][4], acc[ri][5], acc[ri][6], acc[ri][7]);
            }
        }
    }
}

// ---------------- 5. pull-mode gather + self-loop + bias + PReLU ------------
__global__ __launch_bounds__(256) void k_gather(const int* __restrict__ rowptr,
                                                const int* __restrict__ col,
                                                const float* __restrict__ dinv,
                                                const float* __restrict__ H,
                                                const float* __restrict__ b,
                                                const float* __restrict__ pa,
                                                float* __restrict__ out) {
    int node = blockIdx.x * 8 + (threadIdx.x >> 5);
    int lane = threadIdx.x & 31;
    if (node >= N_NODES) return;

    const float4* H4 = (const float4*)H;
    float di = dinv[node];

    float4 hs = H4[(size_t)node * 32 + lane];
    float4 acc = make_float4(hs.x * di, hs.y * di, hs.z * di, hs.w * di);

    int r0 = rowptr[node];
    int r1 = rowptr[node + 1];

    for (int base = r0; base < r1; base += 32) {
        int e    = base + lane;
        int srcL = (e < r1) ? col[e] : 0;
        float sL = (e < r1) ? dinv[srcL] : 0.0f;
        int cnt  = min(32, r1 - base);

        int j = 0;
        for (; j + 8 <= cnt; j += 8) {
            float4 v[8];
            float  sc[8];
#pragma unroll
            for (int t = 0; t < 8; t++) {
                int src = __shfl_sync(0xffffffffu, srcL, j + t);
                sc[t]   = __shfl_sync(0xffffffffu, sL,  j + t);
                v[t]    = H4[(size_t)src * 32 + lane];
            }
#pragma unroll
            for (int t = 0; t < 8; t++) {
                acc.x += v[t].x * sc[t];
                acc.y += v[t].y * sc[t];
                acc.z += v[t].z * sc[t];
                acc.w += v[t].w * sc[t];
            }
        }
        for (; j + 4 <= cnt; j += 4) {
            float4 v[4];
            float  sc[4];
#pragma unroll
            for (int t = 0; t < 4; t++) {
                int src = __shfl_sync(0xffffffffu, srcL, j + t);
                sc[t]   = __shfl_sync(0xffffffffu, sL,  j + t);
                v[t]    = H4[(size_t)src * 32 + lane];
            }
#pragma unroll
            for (int t = 0; t < 4; t++) {
                acc.x += v[t].x * sc[t];
                acc.y += v[t].y * sc[t];
                acc.z += v[t].z * sc[t];
                acc.w += v[t].w * sc[t];
            }
        }
        for (; j < cnt; j++) {
            int   src = __shfl_sync(0xffffffffu, srcL, j);
            float sc  = __shfl_sync(0xffffffffu, sL,  j);
            float4 v  = H4[(size_t)src * 32 + lane];
            acc.x += v.x * sc;
            acc.y += v.y * sc;
            acc.z += v.z * sc;
            acc.w += v.w * sc;
        }
    }

    float4 bb = ((const float4*)b)[lane];
    float4 aa = ((const float4*)pa)[lane];
    float4 o;
    o.x = acc.x * di + bb.x;
    o.y = acc.y * di + bb.y;
    o.z = acc.z * di + bb.z;
    o.w = acc.w * di + bb.w;
    o.x = o.x > 0.f ? o.x : aa.x * o.x;
    o.y = o.y > 0.f ? o.y : aa.y * o.y;
    o.z = o.z > 0.f ? o.z : aa.z * o.z;
    o.w = o.w > 0.f ? o.w : aa.w * o.w;
    ((float4*)out)[(size_t)node * 32 + lane] = o;
}

// ---------------- launch: fork build onto s2, GEMM on capture stream --------
extern "C" void kernel_launch(void* const* d_in, const int* in_sizes, int n_in,
                              void* d_out, int out_size) {
    const float* x  = (const float*)d_in[0];
    const int*   ei = (const int*)d_in[1];     // [2, N_EDGES] int32
    const float* W  = (const float*)d_in[2];
    const float* b  = (const float*)d_in[3];
    const float* pa = (const float*)d_in[4];
    float* out = (float*)d_out;

    int*   deg;    cudaGetSymbolAddress((void**)&deg,    g_deg);
    float* dinv;   cudaGetSymbolAddress((void**)&dinv,   g_dinv);
    int*   rowptr; cudaGetSymbolAddress((void**)&rowptr, g_rowptr);
    int*   cursor; cudaGetSymbolAddress((void**)&cursor, g_cursor);
    int*   col;    cudaGetSymbolAddress((void**)&col,    g_col);
    int*   bsum;   cudaGetSymbolAddress((void**)&bsum,   g_bsum);
    int*   boff;   cudaGetSymbolAddress((void**)&boff,   g_boff);
    float* h;      cudaGetSymbolAddress((void**)&h,      g_h);

    // fork: CSR build on g_s2, GEMM on the capture (default) stream
    cudaEventRecord(g_evFork, 0);
    cudaStreamWaitEvent(g_s2, g_evFork, 0);

    k_zero <<<(N_NODES + 255) / 256, 256, 0, g_s2>>>(deg);
    k_count<<<(N_EDGES + 255) / 256, 256, 0, g_s2>>>(ei, deg);
    k_scan1<<<SCAN_BLOCKS, 256, 0, g_s2>>>(deg, bsum);
    k_scan2<<<1, 32, 0, g_s2>>>(bsum, boff, rowptr);
    k_scan3<<<SCAN_BLOCKS, 256, 0, g_s2>>>(deg, boff, rowptr, cursor, dinv);
    k_fill <<<(N_EDGES + 255) / 256, 256, 0, g_s2>>>(ei, cursor, col);
    cudaEventRecord(g_evJoin, g_s2);

    k_gemm <<<(N_NODES + 127) / 128, 256>>>(x, W, h);

    cudaStreamWaitEvent(0, g_evJoin, 0);
    k_gather<<<(N_NODES + 7) / 8, 256>>>(rowptr, col, dinv, h, b, pa, out);
}

// round 6
// speedup vs baseline: 2.6481x; 1.0064x over previous
#include <cuda_runtime.h>
#include <cstdint>

#define N_NODES 50000
#define N_EDGES 800000
#define D_IN    256
#define D_OUT   128

#define SCAN_BLOCKS ((N_NODES + 1023) / 1024)   // 49

// ---------------- scratch (no allocations allowed) ----------------
__device__ int   g_deg   [N_NODES];
__device__ float g_dinv  [N_NODES];
__device__ int   g_rowptr[N_NODES + 1];
__device__ int   g_cursor[N_NODES];
__device__ int2  g_edge  [N_EDGES];     // {src, __float_as_int(dinv[src])}
__device__ int   g_bsum  [64];
__device__ int   g_boff  [64];
__device__ float g_h     [(size_t)N_NODES * D_OUT];   // 25.6 MB

// ---------------- streams/events for capture-fork (created before capture) --
static cudaStream_t g_s2;
static cudaEvent_t  g_evFork, g_evJoin;
static struct StreamInit {
    StreamInit() {
        cudaStreamCreateWithFlags(&g_s2, cudaStreamNonBlocking);
        cudaEventCreateWithFlags(&g_evFork, cudaEventDisableTiming);
        cudaEventCreateWithFlags(&g_evJoin, cudaEventDisableTiming);
    }
} g_streamInit;

// ---------------- 1a. zero degree ----------------
__global__ void k_zero(int* deg) {
    int i = blockIdx.x * blockDim.x + threadIdx.x;
    if (i < N_NODES) deg[i] = 0;
}

// ---------------- 1b. histogram of dst ----------------
__global__ void k_count(const int* __restrict__ ei, int* deg) {
    int e = blockIdx.x * blockDim.x + threadIdx.x;
    if (e < N_EDGES) atomicAdd(&deg[ei[N_EDGES + e]], 1);
}

// ---------------- 2a. per-block partial sums (1024 deg per block) -----------
__global__ __launch_bounds__(256) void k_scan1(const int* __restrict__ deg,
                                               int* __restrict__ bsum) {
    __shared__ int ws[8];
    int b = blockIdx.x, t = threadIdx.x;
    int base = b * 1024 + t * 4;
    int s = 0;
#pragma unroll
    for (int q = 0; q < 4; q++) {
        int i = base + q;
        if (i < N_NODES) s += deg[i];
    }
    for (int o = 16; o; o >>= 1) s += __shfl_down_sync(0xffffffffu, s, o);
    if ((t & 31) == 0) ws[t >> 5] = s;
    __syncthreads();
    if (t == 0) {
        int v = 0;
#pragma unroll
        for (int w = 0; w < 8; w++) v += ws[w];
        bsum[b] = v;
    }
}

// ---------------- 2b. tiny serial scan of 49 block sums ----------------
__global__ void k_scan2(const int* __restrict__ bsum, int* __restrict__ boff,
                        int* __restrict__ rowptr) {
    if (threadIdx.x == 0) {
        int run = 0;
#pragma unroll
        for (int b = 0; b < SCAN_BLOCKS; b++) {
            boff[b] = run;
            run += bsum[b];
        }
        rowptr[N_NODES] = N_EDGES;
    }
}

// ---------------- 2c. rescan + write rowptr/cursor/dinv ----------------
__global__ __launch_bounds__(256) void k_scan3(const int* __restrict__ deg,
                                               const int* __restrict__ boff,
                                               int* __restrict__ rowptr,
                                               int* __restrict__ cursor,
                                               float* __restrict__ dinv) {
    __shared__ int ws[8];
    int b = blockIdx.x, t = threadIdx.x;
    int base = b * 1024 + t * 4;
    int d[4];
    int s = 0;
#pragma unroll
    for (int q = 0; q < 4; q++) {
        int i = base + q;
        d[q] = (i < N_NODES) ? deg[i] : 0;
        s += d[q];
    }
    int lane = t & 31, w = t >> 5;
    int inc = s;
    for (int o = 1; o < 32; o <<= 1) {
        int v = __shfl_up_sync(0xffffffffu, inc, o);
        if (lane >= o) inc += v;
    }
    if (lane == 31) ws[w] = inc;
    __syncthreads();
    if (t < 8) {
        int v = ws[t];
        int p = v;
        for (int o = 1; o < 8; o <<= 1) {
            int u = __shfl_up_sync(0xffu, p, o);
            if (t >= o) p += u;
        }
        ws[t] = p - v;
    }
    __syncthreads();
    int off = boff[b] + ws[w] + (inc - s);
#pragma unroll
    for (int q = 0; q < 4; q++) {
        int i = base + q;
        if (i < N_NODES) {
            rowptr[i] = off;
            cursor[i] = off;
            dinv[i]   = rsqrtf((float)d[q] + 1.0f);   // +1 = self loop
            off += d[q];
        }
    }
}

// ---------------- 3. bucket fill: col + prefetched dinv[src] ----------------
__global__ void k_fill(const int* __restrict__ ei, int* __restrict__ cursor,
                       const float* __restrict__ dinv, int2* __restrict__ edge) {
    int e = blockIdx.x * blockDim.x + threadIdx.x;
    if (e < N_EDGES) {
        int src = ei[e];
        int dst = ei[N_EDGES + e];
        float s = dinv[src];
        int pos = atomicAdd(&cursor[dst], 1);
        edge[pos] = make_int2(src, __float_as_int(s));
    }
}

// ---------------- 4. GEMM h = x @ W  (128x128x16, double-buffered) ----------
__global__ __launch_bounds__(256) void k_gemm(const float* __restrict__ X,
                                              const float* __restrict__ W,
                                              float* __restrict__ H) {
    __shared__ float Ast[2][16][132];
    __shared__ float Bs [2][16][128];

    const int tid = threadIdx.x;
    const int tx  = tid & 15;
    const int ty  = tid >> 4;
    const int m0  = blockIdx.x * 128;

    float acc[8][8];
#pragma unroll
    for (int i = 0; i < 8; i++)
#pragma unroll
        for (int j = 0; j < 8; j++) acc[i][j] = 0.0f;

    const float4* X4 = (const float4*)X;
    const float4* W4 = (const float4*)W;

#pragma unroll
    for (int p = 0; p < 2; p++) {
        int idx = tid + p * 256;
        int r   = idx >> 2;
        int c4  = idx & 3;
        int gr  = m0 + r;
        float4 v = make_float4(0.f, 0.f, 0.f, 0.f);
        if (gr < N_NODES) v = X4[(size_t)gr * 64 + c4];
        Ast[0][c4 * 4 + 0][r] = v.x;
        Ast[0][c4 * 4 + 1][r] = v.y;
        Ast[0][c4 * 4 + 2][r] = v.z;
        Ast[0][c4 * 4 + 3][r] = v.w;
    }
#pragma unroll
    for (int p = 0; p < 2; p++) {
        int idx = tid + p * 256;
        int r   = idx >> 5;
        int c4  = idx & 31;
        ((float4*)&Bs[0][r][0])[c4] = W4[(size_t)r * 32 + c4];
    }
    __syncthreads();

    int buf = 0;
#pragma unroll 1
    for (int kb = 0; kb < D_IN / 16; kb++) {
        int nbuf = buf ^ 1;
        if (kb + 1 < D_IN / 16) {
            int k0 = (kb + 1) * 16;
#pragma unroll
            for (int p = 0; p < 2; p++) {
                int idx = tid + p * 256;
                int r   = idx >> 2;
                int c4  = idx & 3;
                int gr  = m0 + r;
                float4 v = make_float4(0.f, 0.f, 0.f, 0.f);
                if (gr < N_NODES) v = X4[(size_t)gr * 64 + (k0 >> 2) + c4];
                Ast[nbuf][c4 * 4 + 0][r] = v.x;
                Ast[nbuf][c4 * 4 + 1][r] = v.y;
                Ast[nbuf][c4 * 4 + 2][r] = v.z;
                Ast[nbuf][c4 * 4 + 3][r] = v.w;
            }
#pragma unroll
            for (int p = 0; p < 2; p++) {
                int idx = tid + p * 256;
                int r   = idx >> 5;
                int c4  = idx & 31;
                ((float4*)&Bs[nbuf][r][0])[c4] = W4[(size_t)(k0 + r) * 32 + c4];
            }
        }
#pragma unroll
        for (int k = 0; k < 16; k++) {
            float4 a0 = *(const float4*)&Ast[buf][k][ty * 4];
            float4 a1 = *(const float4*)&Ast[buf][k][ty * 4 + 64];
            float4 b0 = *(const float4*)&Bs[buf][k][tx * 4];
            float4 b1 = *(const float4*)&Bs[buf][k][tx * 4 + 64];
            float ar[8] = {a0.x, a0.y, a0.z, a0.w, a1.x, a1.y, a1.z, a1.w};
            float br[8] = {b0.x, b0.y, b0.z, b0.w, b1.x, b1.y, b1.z, b1.w};
#pragma unroll
            for (int i = 0; i < 8; i++)
#pragma unroll
                for (int j = 0; j < 8; j++)
                    acc[i][j] += ar[i] * br[j];
        }
        __syncthreads();
        buf = nbuf;
    }

    float4* H4 = (float4*)H;
#pragma unroll
    for (int half = 0; half < 2; half++) {
#pragma unroll
        for (int i = 0; i < 4; i++) {
            int gr = m0 + ty * 4 + half * 64 + i;
            if (gr < N_NODES) {
                int ri = half * 4 + i;
                H4[(size_t)gr * 32 + tx] =
                    make_float4(acc[ri][0], acc[ri][1], acc[ri][2], acc[ri][3]);
                H4[(size_t)gr * 32 + tx + 16] =
                    make_float4(acc[ri][4], acc[ri][5], acc[ri][6], acc[ri][7]);
            }
        }
    }
}

// ---------------- 5. gather + self-loop + bias + PReLU ----------------------
// one warp per node; lane owns 4 channels. Edge list carries {src, dinv[src]}
// so the hot loop has NO dependent scalar gathers: 8B coalesced edge load,
// 2 shfls, then 8 independent LDG.128 row fetches (MLP=8).
__global__ __launch_bounds__(256) void k_gather(const int* __restrict__ rowptr,
                                                const int2* __restrict__ edge,
                                                const float* __restrict__ dinv,
                                                const float* __restrict__ H,
                                                const float* __restrict__ b,
                                                const float* __restrict__ pa,
                                                float* __restrict__ out) {
    int node = blockIdx.x * 8 + (threadIdx.x >> 5);
    int lane = threadIdx.x & 31;
    if (node >= N_NODES) return;

    const float4* H4 = (const float4*)H;
    float di = dinv[node];

    float4 hs = H4[(size_t)node * 32 + lane];
    float4 acc = make_float4(hs.x * di, hs.y * di, hs.z * di, hs.w * di);

    int r0 = rowptr[node];
    int r1 = rowptr[node + 1];

    for (int base = r0; base < r1; base += 32) {
        int e   = base + lane;
        int2 eL = (e < r1) ? edge[e] : make_int2(0, 0);
        int cnt = min(32, r1 - base);

        int j = 0;
        for (; j + 8 <= cnt; j += 8) {
            float4 v[8];
            float  sc[8];
#pragma unroll
            for (int t = 0; t < 8; t++) {
                int src = __shfl_sync(0xffffffffu, eL.x, j + t);
                sc[t]   = __int_as_float(__shfl_sync(0xffffffffu, eL.y, j + t));
                v[t]    = H4[(size_t)src * 32 + lane];
            }
#pragma unroll
            for (int t = 0; t < 8; t++) {
                acc.x += v[t].x * sc[t];
                acc.y += v[t].y * sc[t];
                acc.z += v[t].z * sc[t];
                acc.w += v[t].w * sc[t];
            }
        }
        for (; j + 4 <= cnt; j += 4) {
            float4 v[4];
            float  sc[4];
#pragma unroll
            for (int t = 0; t < 4; t++) {
                int src = __shfl_sync(0xffffffffu, eL.x, j + t);
                sc[t]   = __int_as_float(__shfl_sync(0xffffffffu, eL.y, j + t));
                v[t]    = H4[(size_t)src * 32 + lane];
            }
#pragma unroll
            for (int t = 0; t < 4; t++) {
                acc.x += v[t].x * sc[t];
                acc.y += v[t].y * sc[t];
                acc.z += v[t].z * sc[t];
                acc.w += v[t].w * sc[t];
            }
        }
        for (; j < cnt; j++) {
            int   src = __shfl_sync(0xffffffffu, eL.x, j);
            float sc  = __int_as_float(__shfl_sync(0xffffffffu, eL.y, j));
            float4 v  = H4[(size_t)src * 32 + lane];
            acc.x += v.x * sc;
            acc.y += v.y * sc;
            acc.z += v.z * sc;
            acc.w += v.w * sc;
        }
    }

    float4 bb = ((const float4*)b)[lane];
    float4 aa = ((const float4*)pa)[lane];
    float4 o;
    o.x = acc.x * di + bb.x;
    o.y = acc.y * di + bb.y;
    o.z = acc.z * di + bb.z;
    o.w = acc.w * di + bb.w;
    o.x = o.x > 0.f ? o.x : aa.x * o.x;
    o.y = o.y > 0.f ? o.y : aa.y * o.y;
    o.z = o.z > 0.f ? o.z : aa.z * o.z;
    o.w = o.w > 0.f ? o.w : aa.w * o.w;
    ((float4*)out)[(size_t)node * 32 + lane] = o;
}

// ---------------- launch: fork build onto s2, GEMM on capture stream --------
extern "C" void kernel_launch(void* const* d_in, const int* in_sizes, int n_in,
                              void* d_out, int out_size) {
    const float* x  = (const float*)d_in[0];
    const int*   ei = (const int*)d_in[1];     // [2, N_EDGES] int32
    const float* W  = (const float*)d_in[2];
    const float* b  = (const float*)d_in[3];
    const float* pa = (const float*)d_in[4];
    float* out = (float*)d_out;

    int*   deg;    cudaGetSymbolAddress((void**)&deg,    g_deg);
    float* dinv;   cudaGetSymbolAddress((void**)&dinv,   g_dinv);
    int*   rowptr; cudaGetSymbolAddress((void**)&rowptr, g_rowptr);
    int*   cursor; cudaGetSymbolAddress((void**)&cursor, g_cursor);
    int2*  edge;   cudaGetSymbolAddress((void**)&edge,   g_edge);
    int*   bsum;   cudaGetSymbolAddress((void**)&bsum,   g_bsum);
    int*   boff;   cudaGetSymbolAddress((void**)&boff,   g_boff);
    float* h;      cudaGetSymbolAddress((void**)&h,      g_h);

    cudaEventRecord(g_evFork, 0);
    cudaStreamWaitEvent(g_s2, g_evFork, 0);

    k_zero <<<(N_NODES + 255) / 256, 256, 0, g_s2>>>(deg);
    k_count<<<(N_EDGES + 255) / 256, 256, 0, g_s2>>>(ei, deg);
    k_scan1<<<SCAN_BLOCKS, 256, 0, g_s2>>>(deg, bsum);
    k_scan2<<<1, 32, 0, g_s2>>>(bsum, boff, rowptr);
    k_scan3<<<SCAN_BLOCKS, 256, 0, g_s2>>>(deg, boff, rowptr, cursor, dinv);
    k_fill <<<(N_EDGES + 255) / 256, 256, 0, g_s2>>>(ei, cursor, dinv, edge);
    cudaEventRecord(g_evJoin, g_s2);

    k_gemm <<<(N_NODES + 127) / 128, 256>>>(x, W, h);

    cudaStreamWaitEvent(0, g_evJoin, 0);
    k_gather<<<(N_NODES + 7) / 8, 256>>>(rowptr, edge, dinv, h, b, pa, out);
}

// round 7
// speedup vs baseline: 2.8099x; 1.0611x over previous
#include <cuda_runtime.h>
#include <cuda_fp16.h>
#include <cstdint>

#define N_NODES 50000
#define N_EDGES 800000
#define D_IN    256
#define D_OUT   128

#define SCAN_BLOCKS ((N_NODES + 1023) / 1024)   // 49

// ---------------- scratch (no allocations allowed) ----------------
__device__ int    g_deg   [N_NODES];
__device__ float  g_dinv  [N_NODES];
__device__ int    g_rowptr[N_NODES + 1];
__device__ int    g_cursor[N_NODES];
__device__ int2   g_edge  [N_EDGES];     // {src, __float_as_int(dinv[src])}
__device__ int    g_bsum  [64];
__device__ int    g_boff  [64];
__device__ __half g_h     [(size_t)N_NODES * D_OUT];   // 12.8 MB, fp16

// ---------------- streams/events for capture-fork (created before capture) --
static cudaStream_t g_s2;
static cudaEvent_t  g_evFork, g_evJoin;
static struct StreamInit {
    StreamInit() {
        cudaStreamCreateWithFlags(&g_s2, cudaStreamNonBlocking);
        cudaEventCreateWithFlags(&g_evFork, cudaEventDisableTiming);
        cudaEventCreateWithFlags(&g_evJoin, cudaEventDisableTiming);
    }
} g_streamInit;

// ---------------- 1a. zero degree ----------------
__global__ void k_zero(int* deg) {
    int i = blockIdx.x * blockDim.x + threadIdx.x;
    if (i < N_NODES) deg[i] = 0;
}

// ---------------- 1b. histogram of dst ----------------
__global__ void k_count(const int* __restrict__ ei, int* deg) {
    int e = blockIdx.x * blockDim.x + threadIdx.x;
    if (e < N_EDGES) atomicAdd(&deg[ei[N_EDGES + e]], 1);
}

// ---------------- 2a. per-block partial sums ----------------
__global__ __launch_bounds__(256) void k_scan1(const int* __restrict__ deg,
                                               int* __restrict__ bsum) {
    __shared__ int ws[8];
    int b = blockIdx.x, t = threadIdx.x;
    int base = b * 1024 + t * 4;
    int s = 0;
#pragma unroll
    for (int q = 0; q < 4; q++) {
        int i = base + q;
        if (i < N_NODES) s += deg[i];
    }
    for (int o = 16; o; o >>= 1) s += __shfl_down_sync(0xffffffffu, s, o);
    if ((t & 31) == 0) ws[t >> 5] = s;
    __syncthreads();
    if (t == 0) {
        int v = 0;
#pragma unroll
        for (int w = 0; w < 8; w++) v += ws[w];
        bsum[b] = v;
    }
}

// ---------------- 2b. tiny serial scan of 49 block sums ----------------
__global__ void k_scan2(const int* __restrict__ bsum, int* __restrict__ boff,
                        int* __restrict__ rowptr) {
    if (threadIdx.x == 0) {
        int run = 0;
#pragma unroll
        for (int b = 0; b < SCAN_BLOCKS; b++) {
            boff[b] = run;
            run += bsum[b];
        }
        rowptr[N_NODES] = N_EDGES;
    }
}

// ---------------- 2c. rescan + write rowptr/cursor/dinv ----------------
__global__ __launch_bounds__(256) void k_scan3(const int* __restrict__ deg,
                                               const int* __restrict__ boff,
                                               int* __restrict__ rowptr,
                                               int* __restrict__ cursor,
                                               float* __restrict__ dinv) {
    __shared__ int ws[8];
    int b = blockIdx.x, t = threadIdx.x;
    int base = b * 1024 + t * 4;
    int d[4];
    int s = 0;
#pragma unroll
    for (int q = 0; q < 4; q++) {
        int i = base + q;
        d[q] = (i < N_NODES) ? deg[i] : 0;
        s += d[q];
    }
    int lane = t & 31, w = t >> 5;
    int inc = s;
    for (int o = 1; o < 32; o <<= 1) {
        int v = __shfl_up_sync(0xffffffffu, inc, o);
        if (lane >= o) inc += v;
    }
    if (lane == 31) ws[w] = inc;
    __syncthreads();
    if (t < 8) {
        int v = ws[t];
        int p = v;
        for (int o = 1; o < 8; o <<= 1) {
            int u = __shfl_up_sync(0xffu, p, o);
            if (t >= o) p += u;
        }
        ws[t] = p - v;
    }
    __syncthreads();
    int off = boff[b] + ws[w] + (inc - s);
#pragma unroll
    for (int q = 0; q < 4; q++) {
        int i = base + q;
        if (i < N_NODES) {
            rowptr[i] = off;
            cursor[i] = off;
            dinv[i]   = rsqrtf((float)d[q] + 1.0f);   // +1 = self loop
            off += d[q];
        }
    }
}

// ---------------- 3. bucket fill: {src, dinv[src]} ----------------
__global__ void k_fill(const int* __restrict__ ei, int* __restrict__ cursor,
                       const float* __restrict__ dinv, int2* __restrict__ edge) {
    int e = blockIdx.x * blockDim.x + threadIdx.x;
    if (e < N_EDGES) {
        int src = ei[e];
        int dst = ei[N_EDGES + e];
        float s = dinv[src];
        int pos = atomicAdd(&cursor[dst], 1);
        edge[pos] = make_int2(src, __float_as_int(s));
    }
}

// ---------------- 4. GEMM h = x @ W (128x128x16 dbuf), fp16 output ----------
__global__ __launch_bounds__(256) void k_gemm(const float* __restrict__ X,
                                              const float* __restrict__ W,
                                              __half* __restrict__ H) {
    __shared__ float Ast[2][16][132];
    __shared__ float Bs [2][16][128];

    const int tid = threadIdx.x;
    const int tx  = tid & 15;
    const int ty  = tid >> 4;
    const int m0  = blockIdx.x * 128;

    float acc[8][8];
#pragma unroll
    for (int i = 0; i < 8; i++)
#pragma unroll
        for (int j = 0; j < 8; j++) acc[i][j] = 0.0f;

    const float4* X4 = (const float4*)X;
    const float4* W4 = (const float4*)W;

#pragma unroll
    for (int p = 0; p < 2; p++) {
        int idx = tid + p * 256;
        int r   = idx >> 2;
        int c4  = idx & 3;
        int gr  = m0 + r;
        float4 v = make_float4(0.f, 0.f, 0.f, 0.f);
        if (gr < N_NODES) v = X4[(size_t)gr * 64 + c4];
        Ast[0][c4 * 4 + 0][r] = v.x;
        Ast[0][c4 * 4 + 1][r] = v.y;
        Ast[0][c4 * 4 + 2][r] = v.z;
        Ast[0][c4 * 4 + 3][r] = v.w;
    }
#pragma unroll
    for (int p = 0; p < 2; p++) {
        int idx = tid + p * 256;
        int r   = idx >> 5;
        int c4  = idx & 31;
        ((float4*)&Bs[0][r][0])[c4] = W4[(size_t)r * 32 + c4];
    }
    __syncthreads();

    int buf = 0;
#pragma unroll 1
    for (int kb = 0; kb < D_IN / 16; kb++) {
        int nbuf = buf ^ 1;
        if (kb + 1 < D_IN / 16) {
            int k0 = (kb + 1) * 16;
#pragma unroll
            for (int p = 0; p < 2; p++) {
                int idx = tid + p * 256;
                int r   = idx >> 2;
                int c4  = idx & 3;
                int gr  = m0 + r;
                float4 v = make_float4(0.f, 0.f, 0.f, 0.f);
                if (gr < N_NODES) v = X4[(size_t)gr * 64 + (k0 >> 2) + c4];
                Ast[nbuf][c4 * 4 + 0][r] = v.x;
                Ast[nbuf][c4 * 4 + 1][r] = v.y;
                Ast[nbuf][c4 * 4 + 2][r] = v.z;
                Ast[nbuf][c4 * 4 + 3][r] = v.w;
            }
#pragma unroll
            for (int p = 0; p < 2; p++) {
                int idx = tid + p * 256;
                int r   = idx >> 5;
                int c4  = idx & 31;
                ((float4*)&Bs[nbuf][r][0])[c4] = W4[(size_t)(k0 + r) * 32 + c4];
            }
        }
#pragma unroll
        for (int k = 0; k < 16; k++) {
            float4 a0 = *(const float4*)&Ast[buf][k][ty * 4];
            float4 a1 = *(const float4*)&Ast[buf][k][ty * 4 + 64];
            float4 b0 = *(const float4*)&Bs[buf][k][tx * 4];
            float4 b1 = *(const float4*)&Bs[buf][k][tx * 4 + 64];
            float ar[8] = {a0.x, a0.y, a0.z, a0.w, a1.x, a1.y, a1.z, a1.w};
            float br[8] = {b0.x, b0.y, b0.z, b0.w, b1.x, b1.y, b1.z, b1.w};
#pragma unroll
            for (int i = 0; i < 8; i++)
#pragma unroll
                for (int j = 0; j < 8; j++)
                    acc[i][j] += ar[i] * br[j];
        }
        __syncthreads();
        buf = nbuf;
    }

    // epilogue: convert to fp16, row = 32 uint2 (4 halves each)
    uint2* H2 = (uint2*)H;
#pragma unroll
    for (int half = 0; half < 2; half++) {
#pragma unroll
        for (int i = 0; i < 4; i++) {
            int gr = m0 + ty * 4 + half * 64 + i;
            if (gr < N_NODES) {
                int ri = half * 4 + i;
                __half2 p0 = __floats2half2_rn(acc[ri][0], acc[ri][1]);
                __half2 p1 = __floats2half2_rn(acc[ri][2], acc[ri][3]);
                __half2 p2 = __floats2half2_rn(acc[ri][4], acc[ri][5]);
                __half2 p3 = __floats2half2_rn(acc[ri][6], acc[ri][7]);
                uint2 u0, u1;
                u0.x = *(unsigned*)&p0; u0.y = *(unsigned*)&p1;
                u1.x = *(unsigned*)&p2; u1.y = *(unsigned*)&p3;
                H2[(size_t)gr * 32 + tx]      = u0;
                H2[(size_t)gr * 32 + tx + 16] = u1;
            }
        }
    }
}

// ---------------- 5. gather (fp16 rows) + self-loop + bias + PReLU ----------
// one warp per node; lane owns 4 channels (8B fp16). MLP=8 batches.
__global__ __launch_bounds__(256) void k_gather(const int* __restrict__ rowptr,
                                                const int2* __restrict__ edge,
                                                const float* __restrict__ dinv,
                                                const __half* __restrict__ H,
                                                const float* __restrict__ b,
                                                const float* __restrict__ pa,
                                                float* __restrict__ out) {
    int node = blockIdx.x * 8 + (threadIdx.x >> 5);
    int lane = threadIdx.x & 31;
    if (node >= N_NODES) return;

    const uint2* H2 = (const uint2*)H;
    float di = dinv[node];

    // self-loop term
    uint2 sraw = H2[(size_t)node * 32 + lane];
    float2 s01 = __half22float2(*reinterpret_cast<const __half2*>(&sraw.x));
    float2 s23 = __half22float2(*reinterpret_cast<const __half2*>(&sraw.y));
    float4 acc = make_float4(s01.x * di, s01.y * di, s23.x * di, s23.y * di);

    int r0 = rowptr[node];
    int r1 = rowptr[node + 1];

    for (int base = r0; base < r1; base += 32) {
        int e   = base + lane;
        int2 eL = (e < r1) ? edge[e] : make_int2(0, 0);
        int cnt = min(32, r1 - base);

        int j = 0;
        for (; j + 8 <= cnt; j += 8) {
            uint2 v[8];
            float sc[8];
#pragma unroll
            for (int t = 0; t < 8; t++) {
                int src = __shfl_sync(0xffffffffu, eL.x, j + t);
                sc[t]   = __int_as_float(__shfl_sync(0xffffffffu, eL.y, j + t));
                v[t]    = H2[(size_t)src * 32 + lane];
            }
#pragma unroll
            for (int t = 0; t < 8; t++) {
                float2 f01 = __half22float2(*reinterpret_cast<const __half2*>(&v[t].x));
                float2 f23 = __half22float2(*reinterpret_cast<const __half2*>(&v[t].y));
                acc.x += f01.x * sc[t];
                acc.y += f01.y * sc[t];
                acc.z += f23.x * sc[t];
                acc.w += f23.y * sc[t];
            }
        }
        for (; j + 4 <= cnt; j += 4) {
            uint2 v[4];
            float sc[4];
#pragma unroll
            for (int t = 0; t < 4; t++) {
                int src = __shfl_sync(0xffffffffu, eL.x, j + t);
                sc[t]   = __int_as_float(__shfl_sync(0xffffffffu, eL.y, j + t));
                v[t]    = H2[(size_t)src * 32 + lane];
            }
#pragma unroll
            for (int t = 0; t < 4; t++) {
                float2 f01 = __half22float2(*reinterpret_cast<const __half2*>(&v[t].x));
                float2 f23 = __half22float2(*reinterpret_cast<const __half2*>(&v[t].y));
                acc.x += f01.x * sc[t];
                acc.y += f01.y * sc[t];
                acc.z += f23.x * sc[t];
                acc.w += f23.y * sc[t];
            }
        }
        for (; j < cnt; j++) {
            int   src = __shfl_sync(0xffffffffu, eL.x, j);
            float sc  = __int_as_float(__shfl_sync(0xffffffffu, eL.y, j));
            uint2 v   = H2[(size_t)src * 32 + lane];
            float2 f01 = __half22float2(*reinterpret_cast<const __half2*>(&v.x));
            float2 f23 = __half22float2(*reinterpret_cast<const __half2*>(&v.y));
            acc.x += f01.x * sc;
            acc.y += f01.y * sc;
            acc.z += f23.x * sc;
            acc.w += f23.y * sc;
        }
    }

    float4 bb = ((const float4*)b)[lane];
    float4 aa = ((const float4*)pa)[lane];
    float4 o;
    o.x = acc.x * di + bb.x;
    o.y = acc.y * di + bb.y;
    o.z = acc.z * di + bb.z;
    o.w = acc.w * di + bb.w;
    o.x = o.x > 0.f ? o.x : aa.x * o.x;
    o.y = o.y > 0.f ? o.y : aa.y * o.y;
    o.z = o.z > 0.f ? o.z : aa.z * o.z;
    o.w = o.w > 0.f ? o.w : aa.w * o.w;
    ((float4*)out)[(size_t)node * 32 + lane] = o;
}

// ---------------- launch: fork build onto s2, GEMM on capture stream --------
extern "C" void kernel_launch(void* const* d_in, const int* in_sizes, int n_in,
                              void* d_out, int out_size) {
    const float* x  = (const float*)d_in[0];
    const int*   ei = (const int*)d_in[1];     // [2, N_EDGES] int32
    const float* W  = (const float*)d_in[2];
    const float* b  = (const float*)d_in[3];
    const float* pa = (const float*)d_in[4];
    float* out = (float*)d_out;

    int*    deg;    cudaGetSymbolAddress((void**)&deg,    g_deg);
    float*  dinv;   cudaGetSymbolAddress((void**)&dinv,   g_dinv);
    int*    rowptr; cudaGetSymbolAddress((void**)&rowptr, g_rowptr);
    int*    cursor; cudaGetSymbolAddress((void**)&cursor, g_cursor);
    int2*   edge;   cudaGetSymbolAddress((void**)&edge,   g_edge);
    int*    bsum;   cudaGetSymbolAddress((void**)&bsum,   g_bsum);
    int*    boff;   cudaGetSymbolAddress((void**)&boff,   g_boff);
    __half* h;      cudaGetSymbolAddress((void**)&h,      g_h);

    cudaEventRecord(g_evFork, 0);
    cudaStreamWaitEvent(g_s2, g_evFork, 0);

    k_zero <<<(N_NODES + 255) / 256, 256, 0, g_s2>>>(deg);
    k_count<<<(N_EDGES + 255) / 256, 256, 0, g_s2>>>(ei, deg);
    k_scan1<<<SCAN_BLOCKS, 256, 0, g_s2>>>(deg, bsum);
    k_scan2<<<1, 32, 0, g_s2>>>(bsum, boff, rowptr);
    k_scan3<<<SCAN_BLOCKS, 256, 0, g_s2>>>(deg, boff, rowptr, cursor, dinv);
    k_fill <<<(N_EDGES + 255) / 256, 256, 0, g_s2>>>(ei, cursor, dinv, edge);
    cudaEventRecord(g_evJoin, g_s2);

    k_gemm <<<(N_NODES + 127) / 128, 256>>>(x, W, h);

    cudaStreamWaitEvent(0, g_evJoin, 0);
    k_gather<<<(N_NODES + 7) / 8, 256>>>(rowptr, edge, dinv, h, b, pa, out);
}

// round 8
// speedup vs baseline: 4.6172x; 1.6432x over previous
#include <cuda_runtime.h>
#include <cuda_fp16.h>
#include <cstdint>

#define N_NODES 50000
#define N_EDGES 800000
#define D_IN    256
#define D_OUT   128

#define SCAN_BLOCKS ((N_NODES + 1023) / 1024)   // 49

// ---------------- scratch (no allocations allowed) ----------------
__device__ int    g_deg   [N_NODES];
__device__ float  g_dinv  [N_NODES];
__device__ int    g_rowptr[N_NODES + 1];
__device__ int    g_cursor[N_NODES];
__device__ int2   g_edge  [N_EDGES];     // {src, __float_as_int(dinv[src])}
__device__ int    g_bsum  [64];
__device__ __align__(16) __half g_h[(size_t)N_NODES * D_OUT];   // 12.8 MB

// ---------------- streams/events (created before capture) ----------------
static cudaStream_t g_s2;
static cudaEvent_t  g_evFork, g_evJoin;
static struct StreamInit {
    StreamInit() {
        cudaStreamCreateWithFlags(&g_s2, cudaStreamNonBlocking);
        cudaEventCreateWithFlags(&g_evFork, cudaEventDisableTiming);
        cudaEventCreateWithFlags(&g_evJoin, cudaEventDisableTiming);
    }
} g_streamInit;

// ---------------- 1. histogram of dst ----------------
__global__ void k_count(const int* __restrict__ ei, int* deg) {
    int e = blockIdx.x * blockDim.x + threadIdx.x;
    if (e < N_EDGES) atomicAdd(&deg[ei[N_EDGES + e]], 1);
}

// ---------------- 2a. per-block partial sums ----------------
__global__ __launch_bounds__(256) void k_scan1(const int* __restrict__ deg,
                                               int* __restrict__ bsum,
                                               int* __restrict__ rowptr) {
    __shared__ int ws[8];
    int b = blockIdx.x, t = threadIdx.x;
    int base = b * 1024 + t * 4;
    int s = 0;
#pragma unroll
    for (int q = 0; q < 4; q++) {
        int i = base + q;
        if (i < N_NODES) s += deg[i];
    }
    for (int o = 16; o; o >>= 1) s += __shfl_down_sync(0xffffffffu, s, o);
    if ((t & 31) == 0) ws[t >> 5] = s;
    __syncthreads();
    if (t == 0) {
        int v = 0;
#pragma unroll
        for (int w = 0; w < 8; w++) v += ws[w];
        bsum[b] = v;
        if (b == 0) rowptr[N_NODES] = N_EDGES;
    }
}

// ---------------- 2b. rescan + write rowptr/cursor/dinv (boff inline) -------
__global__ __launch_bounds__(256) void k_scan3(const int* __restrict__ deg,
                                               const int* __restrict__ bsum,
                                               int* __restrict__ rowptr,
                                               int* __restrict__ cursor,
                                               float* __restrict__ dinv) {
    __shared__ int ws[8];
    __shared__ int red[64];
    int b = blockIdx.x, t = threadIdx.x;

    // block offset = sum of bsum[0..b-1]
    if (t < 64) red[t] = (t < b) ? bsum[t] : 0;
    __syncthreads();
    if (t < 32) {
        int s = red[t] + red[t + 32];
        for (int o = 16; o; o >>= 1) s += __shfl_down_sync(0xffffffffu, s, o);
        if (t == 0) red[0] = s;
    }
    __syncthreads();
    int boff_val = red[0];

    int base = b * 1024 + t * 4;
    int d[4];
    int s = 0;
#pragma unroll
    for (int q = 0; q < 4; q++) {
        int i = base + q;
        d[q] = (i < N_NODES) ? deg[i] : 0;
        s += d[q];
    }
    int lane = t & 31, w = t >> 5;
    int inc = s;
    for (int o = 1; o < 32; o <<= 1) {
        int v = __shfl_up_sync(0xffffffffu, inc, o);
        if (lane >= o) inc += v;
    }
    if (lane == 31) ws[w] = inc;
    __syncthreads();
    if (t < 8) {
        int v = ws[t];
        int p = v;
        for (int o = 1; o < 8; o <<= 1) {
            int u = __shfl_up_sync(0xffu, p, o);
            if (t >= o) p += u;
        }
        ws[t] = p - v;
    }
    __syncthreads();
    int off = boff_val + ws[w] + (inc - s);
#pragma unroll
    for (int q = 0; q < 4; q++) {
        int i = base + q;
        if (i < N_NODES) {
            rowptr[i] = off;
            cursor[i] = off;
            dinv[i]   = rsqrtf((float)d[q] + 1.0f);   // +1 = self loop
            off += d[q];
        }
    }
}

// ---------------- 3. bucket fill: {src, dinv[src]} ----------------
__global__ void k_fill(const int* __restrict__ ei, int* __restrict__ cursor,
                       const float* __restrict__ dinv, int2* __restrict__ edge) {
    int e = blockIdx.x * blockDim.x + threadIdx.x;
    if (e < N_EDGES) {
        int src = ei[e];
        int dst = ei[N_EDGES + e];
        float s = dinv[src];
        int pos = atomicAdd(&cursor[dst], 1);
        edge[pos] = make_int2(src, __float_as_int(s));
    }
}

// ---------------- 4. GEMM h = x @ W via fp16 mma.sync (fp32 accum) ----------
// 128x128 block tile, 8 warps, warp tile 16x128, K chunks of 16.
// smem: Wp half2[128][136] (k-pairs, conflict-free) + A dbuf half[2][128][24].
#define WP_HALF2   (128 * 136)                 // 17408 half2 = 69632 B
#define A_STRIDE   24
#define A_STAGE    (128 * A_STRIDE)            // halves per stage
#define GEMM_SMEM  (WP_HALF2 * 4 + 2 * A_STAGE * 2)   // 81920 B

__global__ __launch_bounds__(256) void k_gemm16(const float* __restrict__ X,
                                                const float* __restrict__ W,
                                                __half* __restrict__ H) {
    extern __shared__ char smem_raw[];
    half2*  Wp = (half2*)smem_raw;                       // [128][136]
    __half* As = (__half*)(smem_raw + WP_HALF2 * 4);     // [2][128][24]

    const int tid  = threadIdx.x;
    const int warp = tid >> 5;
    const int lane = tid & 31;
    const int g    = lane >> 2;      // 0..7
    const int tig  = lane & 3;       // 0..3
    const int m0   = blockIdx.x * 128;

    const float4* X4 = (const float4*)X;   // row stride 64
    const float4* W4 = (const float4*)W;   // row stride 32

    // ---- load W into smem as k-pair half2: Wp[kp][n] = (W[2kp][n], W[2kp+1][n])
#pragma unroll
    for (int i = 0; i < 16; i++) {
        int item = tid + i * 256;          // 0..4095
        int kp   = item >> 5;              // 0..127
        int n4   = item & 31;              // float4 col
        float4 a = W4[(size_t)(2 * kp) * 32 + n4];
        float4 c = W4[(size_t)(2 * kp + 1) * 32 + n4];
        half2 h0 = __floats2half2_rn(a.x, c.x);
        half2 h1 = __floats2half2_rn(a.y, c.y);
        half2 h2 = __floats2half2_rn(a.z, c.z);
        half2 h3 = __floats2half2_rn(a.w, c.w);
        half2* dst = &Wp[kp * 136 + n4 * 4];
        uint4 pack;
        pack.x = *(unsigned*)&h0; pack.y = *(unsigned*)&h1;
        pack.z = *(unsigned*)&h2; pack.w = *(unsigned*)&h3;
        *(uint4*)dst = pack;
    }

    // ---- prologue: A stage 0 (k0 = 0)
#pragma unroll
    for (int p = 0; p < 2; p++) {
        int idx = tid + p * 256;           // 0..511
        int r   = idx >> 2;                // 0..127
        int c4  = idx & 3;                 // 0..3
        int gr  = m0 + r;
        float4 v = make_float4(0.f, 0.f, 0.f, 0.f);
        if (gr < N_NODES) v = X4[(size_t)gr * 64 + c4];
        half2 h01 = __floats2half2_rn(v.x, v.y);
        half2 h23 = __floats2half2_rn(v.z, v.w);
        uint2 u; u.x = *(unsigned*)&h01; u.y = *(unsigned*)&h23;
        *(uint2*)(As + r * A_STRIDE + c4 * 4) = u;
    }
    __syncthreads();

    float acc[16][4];
#pragma unroll
    for (int nt = 0; nt < 16; nt++)
#pragma unroll
        for (int j = 0; j < 4; j++) acc[nt][j] = 0.0f;

    const int rowA = warp * 16 + g;

    int buf = 0;
#pragma unroll 1
    for (int ks = 0; ks < 16; ks++) {
        // prefetch next A stage into regs
        float4 pre[2];
        if (ks + 1 < 16) {
            int k0n = (ks + 1) * 16;
#pragma unroll
            for (int p = 0; p < 2; p++) {
                int idx = tid + p * 256;
                int r   = idx >> 2;
                int c4  = idx & 3;
                int gr  = m0 + r;
                pre[p] = make_float4(0.f, 0.f, 0.f, 0.f);
                if (gr < N_NODES) pre[p] = X4[(size_t)gr * 64 + (k0n >> 2) + c4];
            }
        }

        // A fragment for this warp (m16 k16)
        const __half* Ab = As + buf * A_STAGE;
        unsigned a0 = *(const unsigned*)(Ab + rowA * A_STRIDE + 2 * tig);
        unsigned a1 = *(const unsigned*)(Ab + (rowA + 8) * A_STRIDE + 2 * tig);
        unsigned a2 = *(const unsigned*)(Ab + rowA * A_STRIDE + 2 * tig + 8);
        unsigned a3 = *(const unsigned*)(Ab + (rowA + 8) * A_STRIDE + 2 * tig + 8);

        int k0h = ks * 8;   // k0/2
#pragma unroll
        for (int nt = 0; nt < 16; nt++) {
            int n0 = nt * 8;
            unsigned b0 = *(const unsigned*)&Wp[(k0h + tig) * 136 + n0 + g];
            unsigned b1 = *(const unsigned*)&Wp[(k0h + 4 + tig) * 136 + n0 + g];
            asm volatile(
                "mma.sync.aligned.m16n8k16.row.col.f32.f16.f16.f32 "
                "{%0,%1,%2,%3}, {%4,%5,%6,%7}, {%8,%9}, {%0,%1,%2,%3};\n"
                : "+f"(acc[nt][0]), "+f"(acc[nt][1]),
                  "+f"(acc[nt][2]), "+f"(acc[nt][3])
                : "r"(a0), "r"(a1), "r"(a2), "r"(a3), "r"(b0), "r"(b1));
        }

        if (ks + 1 < 16) {
            int nbuf = buf ^ 1;
#pragma unroll
            for (int p = 0; p < 2; p++) {
                int idx = tid + p * 256;
                int r   = idx >> 2;
                int c4  = idx & 3;
                half2 h01 = __floats2half2_rn(pre[p].x, pre[p].y);
                half2 h23 = __floats2half2_rn(pre[p].z, pre[p].w);
                uint2 u; u.x = *(unsigned*)&h01; u.y = *(unsigned*)&h23;
                *(uint2*)(As + nbuf * A_STAGE + r * A_STRIDE + c4 * 4) = u;
            }
            __syncthreads();
            buf = nbuf;
        }
    }

    // ---- epilogue: fp32 acc -> fp16 H
    int r0 = m0 + rowA;
#pragma unroll
    for (int nt = 0; nt < 16; nt++) {
        int col = nt * 8 + 2 * tig;
        half2 lo = __floats2half2_rn(acc[nt][0], acc[nt][1]);
        half2 hi = __floats2half2_rn(acc[nt][2], acc[nt][3]);
        if (r0 < N_NODES)
            *(unsigned*)(H + (size_t)r0 * 128 + col) = *(unsigned*)&lo;
        if (r0 + 8 < N_NODES)
            *(unsigned*)(H + (size_t)(r0 + 8) * 128 + col) = *(unsigned*)&hi;
    }
}

// ---------------- 5. gather (fp16 rows) + self-loop + bias + PReLU ----------
__global__ __launch_bounds__(256) void k_gather(const int* __restrict__ rowptr,
                                                const int2* __restrict__ edge,
                                                const float* __restrict__ dinv,
                                                const __half* __restrict__ H,
                                                const float* __restrict__ b,
                                                const float* __restrict__ pa,
                                                float* __restrict__ out) {
    int node = blockIdx.x * 8 + (threadIdx.x >> 5);
    int lane = threadIdx.x & 31;
    if (node >= N_NODES) return;

    const uint2* H2 = (const uint2*)H;
    float di = dinv[node];

    uint2 sraw = H2[(size_t)node * 32 + lane];
    float2 s01 = __half22float2(*reinterpret_cast<const __half2*>(&sraw.x));
    float2 s23 = __half22float2(*reinterpret_cast<const __half2*>(&sraw.y));
    float4 acc = make_float4(s01.x * di, s01.y * di, s23.x * di, s23.y * di);

    int r0 = rowptr[node];
    int r1 = rowptr[node + 1];

    for (int base = r0; base < r1; base += 32) {
        int e   = base + lane;
        int2 eL = (e < r1) ? edge[e] : make_int2(0, 0);
        int cnt = min(32, r1 - base);

        int j = 0;
        for (; j + 8 <= cnt; j += 8) {
            uint2 v[8];
            float sc[8];
#pragma unroll
            for (int t = 0; t < 8; t++) {
                int src = __shfl_sync(0xffffffffu, eL.x, j + t);
                sc[t]   = __int_as_float(__shfl_sync(0xffffffffu, eL.y, j + t));
                v[t]    = H2[(size_t)src * 32 + lane];
            }
#pragma unroll
            for (int t = 0; t < 8; t++) {
                float2 f01 = __half22float2(*reinterpret_cast<const __half2*>(&v[t].x));
                float2 f23 = __half22float2(*reinterpret_cast<const __half2*>(&v[t].y));
                acc.x += f01.x * sc[t];
                acc.y += f01.y * sc[t];
                acc.z += f23.x * sc[t];
                acc.w += f23.y * sc[t];
            }
        }
        for (; j + 4 <= cnt; j += 4) {
            uint2 v[4];
            float sc[4];
#pragma unroll
            for (int t = 0; t < 4; t++) {
                int src = __shfl_sync(0xffffffffu, eL.x, j + t);
                sc[t]   = __int_as_float(__shfl_sync(0xffffffffu, eL.y, j + t));
                v[t]    = H2[(size_t)src * 32 + lane];
            }
#pragma unroll
            for (int t = 0; t < 4; t++) {
                float2 f01 = __half22float2(*reinterpret_cast<const __half2*>(&v[t].x));
                float2 f23 = __half22float2(*reinterpret_cast<const __half2*>(&v[t].y));
                acc.x += f01.x * sc[t];
                acc.y += f01.y * sc[t];
                acc.z += f23.x * sc[t];
                acc.w += f23.y * sc[t];
            }
        }
        for (; j < cnt; j++) {
            int   src = __shfl_sync(0xffffffffu, eL.x, j);
            float sc  = __int_as_float(__shfl_sync(0xffffffffu, eL.y, j));
            uint2 v   = H2[(size_t)src * 32 + lane];
            float2 f01 = __half22float2(*reinterpret_cast<const __half2*>(&v.x));
            float2 f23 = __half22float2(*reinterpret_cast<const __half2*>(&v.y));
            acc.x += f01.x * sc;
            acc.y += f01.y * sc;
            acc.z += f23.x * sc;
            acc.w += f23.y * sc;
        }
    }

    float4 bb = ((const float4*)b)[lane];
    float4 aa = ((const float4*)pa)[lane];
    float4 o;
    o.x = acc.x * di + bb.x;
    o.y = acc.y * di + bb.y;
    o.z = acc.z * di + bb.z;
    o.w = acc.w * di + bb.w;
    o.x = o.x > 0.f ? o.x : aa.x * o.x;
    o.y = o.y > 0.f ? o.y : aa.y * o.y;
    o.z = o.z > 0.f ? o.z : aa.z * o.z;
    o.w = o.w > 0.f ? o.w : aa.w * o.w;
    ((float4*)out)[(size_t)node * 32 + lane] = o;
}

// ---------------- launch ----------------
extern "C" void kernel_launch(void* const* d_in, const int* in_sizes, int n_in,
                              void* d_out, int out_size) {
    const float* x  = (const float*)d_in[0];
    const int*   ei = (const int*)d_in[1];     // [2, N_EDGES] int32
    const float* W  = (const float*)d_in[2];
    const float* b  = (const float*)d_in[3];
    const float* pa = (const float*)d_in[4];
    float* out = (float*)d_out;

    int*    deg;    cudaGetSymbolAddress((void**)&deg,    g_deg);
    float*  dinv;   cudaGetSymbolAddress((void**)&dinv,   g_dinv);
    int*    rowptr; cudaGetSymbolAddress((void**)&rowptr, g_rowptr);
    int*    cursor; cudaGetSymbolAddress((void**)&cursor, g_cursor);
    int2*   edge;   cudaGetSymbolAddress((void**)&edge,   g_edge);
    int*    bsum;   cudaGetSymbolAddress((void**)&bsum,   g_bsum);
    __half* h;      cudaGetSymbolAddress((void**)&h,      g_h);

    cudaFuncSetAttribute(k_gemm16, cudaFuncAttributeMaxDynamicSharedMemorySize,
                         GEMM_SMEM);

    cudaEventRecord(g_evFork, 0);
    cudaStreamWaitEvent(g_s2, g_evFork, 0);

    cudaMemsetAsync(deg, 0, N_NODES * sizeof(int), g_s2);
    k_count<<<(N_EDGES + 255) / 256, 256, 0, g_s2>>>(ei, deg);
    k_scan1<<<SCAN_BLOCKS, 256, 0, g_s2>>>(deg, bsum, rowptr);
    k_scan3<<<SCAN_BLOCKS, 256, 0, g_s2>>>(deg, bsum, rowptr, cursor, dinv);
    k_fill <<<(N_EDGES + 255) / 256, 256, 0, g_s2>>>(ei, cursor, dinv, edge);
    cudaEventRecord(g_evJoin, g_s2);

    k_gemm16<<<(N_NODES + 127) / 128, 256, GEMM_SMEM>>>(x, W, h);

    cudaStreamWaitEvent(0, g_evJoin, 0);
    k_gather<<<(N_NODES + 7) / 8, 256>>>(rowptr, edge, dinv, h, b, pa, out);
}